// round 11
// baseline (speedup 1.0000x reference)
#include <cuda_runtime.h>
#include <cstdint>

#define Bsz 4
#define Sl 4096
#define Dm 1024
#define Hh 16
#define HD 64
#define BH (Bsz * Hh)
#define KVSPLIT 8
#define QBLKS 512

// GEMM-D tiling: CTA 128x256, 8 warps (2x4), warp tile 64x64, BK=32, NS=3
#define TM 128
#define TN 256
#define BK 32
#define NS 3
#define NCHUNK (Dm / BK)
#define KPAD 36
#define A_FLOATS (TM * KPAD)
#define B_FLOATS (TN * KPAD)
#define STAGE_FLOATS (A_FLOATS + B_FLOATS)
#define SMEM_DYN (NS * STAGE_FLOATS * 4)   // 165888 B

// Scratch (allocation-free rule: device globals)
__device__ float g_KV_part[16 * BH * HD * HD];
__device__ float g_KV[BH * HD * HD];
__device__ float g_W2[Bsz * Dm * Dm];           // tf32-bit-pattern floats
__device__ float g_Qtf[(size_t)Bsz * Sl * Dm];  // tf32-bit-pattern Q

// ---------------------------------------------------------------------------
// helpers
// ---------------------------------------------------------------------------
__device__ __forceinline__ uint32_t smem_u32(const void* p) {
    uint32_t a;
    asm("{ .reg .u64 t; cvta.to.shared.u64 t, %1; cvt.u32.u64 %0, t; }"
        : "=r"(a) : "l"(p));
    return a;
}
__device__ __forceinline__ void cp16(uint32_t dst, const void* src) {
    asm volatile("cp.async.cg.shared.global [%0], [%1], 16;" :: "r"(dst), "l"(src));
}
__device__ __forceinline__ uint32_t f2tf32(float f) {
    uint32_t r;
    asm("cvt.rna.tf32.f32 %0, %1;" : "=r"(r) : "f"(f));
    return r;
}
__device__ __forceinline__ void ldsm4(uint32_t* d, uint32_t addr) {
    asm volatile("ldmatrix.sync.aligned.m8n8.x4.shared.b16 {%0,%1,%2,%3}, [%4];"
        : "=r"(d[0]), "=r"(d[1]), "=r"(d[2]), "=r"(d[3]) : "r"(addr));
}
__device__ __forceinline__ void mma_tf32_16n8k8(float* c, uint32_t a0, uint32_t a1,
                                                uint32_t a2, uint32_t a3,
                                                uint32_t b0, uint32_t b1) {
    asm volatile(
        "mma.sync.aligned.m16n8k8.row.col.f32.tf32.tf32.f32 "
        "{%0,%1,%2,%3}, {%4,%5,%6,%7}, {%8,%9}, {%0,%1,%2,%3};"
        : "+f"(c[0]), "+f"(c[1]), "+f"(c[2]), "+f"(c[3])
        : "r"(a0), "r"(a1), "r"(a2), "r"(a3), "r"(b0), "r"(b1));
}

// ---------------------------------------------------------------------------
// Kernel A (fused): blocks [0, BH*KVSPLIT): tensor-core partial KV;
// blocks [BH*KVSPLIT, +QBLKS): Q -> tf32 bit patterns (HBM-bound; overlaps)
// ---------------------------------------------------------------------------
__global__ __launch_bounds__(256) void kv_q_kernel(
    const float* __restrict__ K, const float* __restrict__ V,
    const float* __restrict__ Q)
{
    __shared__ float sK[2][16 * 132];
    __shared__ float sV[2][16 * 132];

    const int blk = blockIdx.x;
    const int t   = threadIdx.x;

    if (blk >= BH * KVSPLIT) {
        size_t f4 = (size_t)(blk - BH * KVSPLIT) * 8192 + t;
#pragma unroll 4
        for (int j = 0; j < 32; j++) {
            size_t i = (f4 + (size_t)j * 256) * 4;
            float4 v = *(const float4*)(Q + i);
            float4 o;
            o.x = __uint_as_float(f2tf32(v.x));
            o.y = __uint_as_float(f2tf32(v.y));
            o.z = __uint_as_float(f2tf32(v.z));
            o.w = __uint_as_float(f2tf32(v.w));
            *(float4*)(g_Qtf + i) = o;
        }
        return;
    }

    const int bh  = blk & (BH - 1);
    const int sp  = blk >> 6;
    const int b = bh >> 4, h = bh & 15;

    const int w   = t >> 5, lid = t & 31;
    const int wg  = w >> 2;
    const int wq  = w & 3;
    const int wm  = wq >> 1;
    const int wn  = wq & 1;
    const int g   = lid >> 2;
    const int tig = lid & 3;

    const float* Kb = K + ((size_t)b * Sl) * Dm + h * HD;
    const float* Vb = V + ((size_t)b * Sl) * Dm + h * HD;
    const int s0 = sp * (Sl / KVSPLIT);

    float acc[2][4][4] = {};

    const int sr = t >> 2;
    const int cg = sr >> 5;
    const int sl = sr & 31;

    for (int it = 0; it < (Sl / KVSPLIT) / 64; it++) {
        size_t grow = (size_t)(s0 + it * 64 + sr) * Dm;
#pragma unroll
        for (int j = 0; j < 4; j++) {
            int db = (t & 3) + j * 4;
            float4 kv = *(const float4*)(Kb + grow + db * 4);
            float4 vv = *(const float4*)(Vb + grow + db * 4);
            float4 ko, vo;
            ko.x = __uint_as_float(f2tf32(kv.x));
            ko.y = __uint_as_float(f2tf32(kv.y));
            ko.z = __uint_as_float(f2tf32(kv.z));
            ko.w = __uint_as_float(f2tf32(kv.w));
            vo.x = __uint_as_float(f2tf32(vv.x));
            vo.y = __uint_as_float(f2tf32(vv.y));
            vo.z = __uint_as_float(f2tf32(vv.z));
            vo.w = __uint_as_float(f2tf32(vv.w));
            *(float4*)&sK[cg][db * 132 + sl * 4] = ko;
            *(float4*)&sV[cg][db * 132 + sl * 4] = vo;
        }
        __syncthreads();

        const float* Kt = sK[wg];
        const float* Vt = sV[wg];
#pragma unroll
        for (int ks = 0; ks < 4; ks++) {
            const int k0 = ks * 8;
            uint32_t a[2][4];
#pragma unroll
            for (int mi = 0; mi < 2; mi++) {
                int d = wm * 32 + mi * 16 + g;
                int i0 = (d >> 2) * 132 + (k0 + tig) * 4 + (d & 3);
                a[mi][0] = __float_as_uint(Kt[i0]);
                a[mi][1] = __float_as_uint(Kt[i0 + 264]);
                a[mi][2] = __float_as_uint(Kt[i0 + 16]);
                a[mi][3] = __float_as_uint(Kt[i0 + 280]);
            }
#pragma unroll
            for (int ni = 0; ni < 4; ni++) {
                int e = wn * 32 + ni * 8 + g;
                int i0 = (e >> 2) * 132 + (k0 + tig) * 4 + (e & 3);
                uint32_t b0 = __float_as_uint(Vt[i0]);
                uint32_t b1 = __float_as_uint(Vt[i0 + 16]);
#pragma unroll
                for (int mi = 0; mi < 2; mi++)
                    mma_tf32_16n8k8(acc[mi][ni],
                                    a[mi][0], a[mi][1], a[mi][2], a[mi][3],
                                    b0, b1);
            }
        }
        __syncthreads();
    }

    float* out = g_KV_part + ((size_t)(sp * 2 + wg) * BH + bh) * (HD * HD);
#pragma unroll
    for (int mi = 0; mi < 2; mi++) {
        int d = wm * 32 + mi * 16 + g;
#pragma unroll
        for (int ni = 0; ni < 4; ni++) {
            int e = wn * 32 + ni * 8 + tig * 2;
            *(float2*)(out + d * HD + e)       = make_float2(acc[mi][ni][0], acc[mi][ni][1]);
            *(float2*)(out + (d + 8) * HD + e) = make_float2(acc[mi][ni][2], acc[mi][ni][3]);
        }
    }
}

// ---------------------------------------------------------------------------
// Kernel B: deterministic reduction of 16 partials
// ---------------------------------------------------------------------------
__global__ __launch_bounds__(256) void kv_reduce_kernel()
{
    int idx = blockIdx.x * 256 + threadIdx.x;
    float s = 0.f;
#pragma unroll
    for (int p = 0; p < 16; p++)
        s += g_KV_part[(size_t)p * (BH * HD * HD) + idx];
    g_KV[idx] = s;
}

// ---------------------------------------------------------------------------
// Kernel C: W2[b][o][h*64+d] = sum_e KV[b,h,d,e] * W[o*Dm + h*64 + e]
// ---------------------------------------------------------------------------
__global__ __launch_bounds__(128) void w2_kernel(const float* __restrict__ W)
{
    __shared__ float KVt[64][64];
    __shared__ float WsT[64][128];

    const int bh = blockIdx.x;
    const int b = bh >> 4, h = bh & 15;
    const int t = threadIdx.x;
    const int o_base = blockIdx.y * 128;

#pragma unroll
    for (int i = 0; i < 8; i++) {
        int idx = t + i * 128;
        int rd = idx & 63;
        int c4 = (idx >> 6) * 4;
        float4 v = *(const float4*)(g_KV + (size_t)bh * 4096 + rd * 64 + c4);
        KVt[c4 + 0][rd] = v.x; KVt[c4 + 1][rd] = v.y;
        KVt[c4 + 2][rd] = v.z; KVt[c4 + 3][rd] = v.w;
    }
#pragma unroll
    for (int i = 0; i < 16; i++) {
        int idx = t + i * 128;
        int ro = idx & 127;
        int c4 = (idx >> 7) * 4;
        float4 v = *(const float4*)(W + (size_t)(o_base + ro) * Dm + h * HD + c4);
        WsT[c4 + 0][ro] = v.x; WsT[c4 + 1][ro] = v.y;
        WsT[c4 + 2][ro] = v.z; WsT[c4 + 3][ro] = v.w;
    }
    __syncthreads();

    const int d0 = (t & 7) * 8;
    const int o0 = (t >> 3) * 8;
    float acc[8][8] = {};
#pragma unroll 4
    for (int e = 0; e < 64; e++) {
        float ww[8], kk[8];
        *(float4*)&ww[0] = *(const float4*)&WsT[e][o0];
        *(float4*)&ww[4] = *(const float4*)&WsT[e][o0 + 4];
        *(float4*)&kk[0] = *(const float4*)&KVt[e][d0];
        *(float4*)&kk[4] = *(const float4*)&KVt[e][d0 + 4];
#pragma unroll
        for (int i = 0; i < 8; i++)
#pragma unroll
            for (int j = 0; j < 8; j++)
                acc[i][j] += ww[i] * kk[j];
    }

#pragma unroll
    for (int i = 0; i < 8; i++) {
        float* dst = g_W2 + ((size_t)b * Dm + (o_base + o0 + i)) * Dm + h * HD + d0;
#pragma unroll
        for (int jj = 0; jj < 2; jj++) {
            float4 o;
            o.x = __uint_as_float(f2tf32(acc[i][jj * 4 + 0]));
            o.y = __uint_as_float(f2tf32(acc[i][jj * 4 + 1]));
            o.z = __uint_as_float(f2tf32(acc[i][jj * 4 + 2]));
            o.w = __uint_as_float(f2tf32(acc[i][jj * 4 + 3]));
            *(float4*)(dst + jj * 4) = o;
        }
    }
}

// ---------------------------------------------------------------------------
// Kernel D: out[b,m,n] = sum_k Qtf[b,m,k]*W2[b,n,k] + bias[n]
// CTA 128x256, 8 warps (2x4), warp tile 64x64 -> halves cross-warp operand
// redundancy (smem 176KB/chunk < mma 2048cyc/chunk: tensor-bound).
// All operands via cp.async + ldmatrix (no in-loop gmem). NS=3, 1 CTA/SM.
// grid (Sl/128, Dm/256, Bsz) = 512 blocks.
// ---------------------------------------------------------------------------
__global__ __launch_bounds__(256, 1) void out_gemm_tc(
    const float* __restrict__ bias, float* __restrict__ Out)
{
    extern __shared__ float smem[];

    const int t   = threadIdx.x;
    const int wid = t >> 5;
    const int lid = t & 31;
    const int g   = lid >> 2;
    const int tig = lid & 3;
    const int wm  = wid >> 2;       // 0..1 (M)
    const int wn  = wid & 3;        // 0..3 (N)

    const int m0 = blockIdx.x * TM;
    const int n0 = blockIdx.y * TN;
    const int b  = blockIdx.z;

    const float* Ag = g_Qtf + (size_t)b * Sl * Dm + (size_t)m0 * Dm;
    const float* Bg = g_W2  + (size_t)b * Dm * Dm + (size_t)n0 * Dm;

    const uint32_t u0 = smem_u32(smem);

    auto load_stage = [&](int s, int k0) {
        uint32_t uA = u0 + (uint32_t)(s * STAGE_FLOATS) * 4;
        uint32_t uB = uA + A_FLOATS * 4;
#pragma unroll
        for (int i = 0; i < 4; i++) {           // A: 128 rows x 32 floats
            int idx = t + (i << 8);
            int row = idx >> 3, c = idx & 7;
            cp16(uA + row * (KPAD * 4) + c * 16, Ag + (size_t)row * Dm + k0 + c * 4);
        }
#pragma unroll
        for (int i = 0; i < 8; i++) {           // B: 256 rows x 32 floats
            int idx = t + (i << 8);
            int row = idx >> 3, c = idx & 7;
            cp16(uB + row * (KPAD * 4) + c * 16, Bg + (size_t)row * Dm + k0 + c * 4);
        }
    };

    float acc[4][8][4] = {};

    load_stage(0, 0);
    asm volatile("cp.async.commit_group;" ::: "memory");
    load_stage(1, BK);
    asm volatile("cp.async.commit_group;" ::: "memory");

    // A: 4 m-tiles of 16 rows within warp's 64-row slice
    const uint32_t aBase = (uint32_t)(wm * 64 + (lid & 15)) * (KPAD * 4)
                         + (uint32_t)(lid >> 4) * 16;
    // B: 4 ldsm.x4 groups of 16 rows within warp's 64-row (n) slice
    const uint32_t bBase = (uint32_t)(wn * 64 + ((lid >> 4) << 3) + (lid & 7)) * (KPAD * 4)
                         + (uint32_t)((lid >> 3) & 1) * 16;

    int s = 0;
    for (int i = 0; i < NCHUNK; i++) {
        asm volatile("cp.async.wait_group 1;" ::: "memory");
        __syncthreads();

        if (i + 2 < NCHUNK) {
            int sn = s + 2; if (sn >= NS) sn -= NS;
            load_stage(sn, (i + 2) * BK);
        }
        asm volatile("cp.async.commit_group;" ::: "memory");

        uint32_t uA = u0 + (uint32_t)(s * STAGE_FLOATS) * 4;
        uint32_t uB = uA + A_FLOATS * 4;

#pragma unroll
        for (int ks = 0; ks < 4; ks++) {
            uint32_t af[4][4];
#pragma unroll
            for (int mi = 0; mi < 4; mi++)
                ldsm4(af[mi], uA + aBase + mi * 16 * (KPAD * 4) + ks * 32);
            uint32_t bf[4][4];
#pragma unroll
            for (int p = 0; p < 4; p++)
                ldsm4(bf[p], uB + bBase + p * 16 * (KPAD * 4) + ks * 32);
#pragma unroll
            for (int mi = 0; mi < 4; mi++)
#pragma unroll
                for (int ni = 0; ni < 8; ni++) {
                    const int p = ni >> 1, q = (ni & 1) * 2;
                    mma_tf32_16n8k8(acc[mi][ni],
                                    af[mi][0], af[mi][1], af[mi][2], af[mi][3],
                                    bf[p][q], bf[p][q + 1]);
                }
        }
        if (++s == NS) s = 0;
    }

    float* C = Out + (size_t)b * Sl * Dm;
#pragma unroll
    for (int mi = 0; mi < 4; mi++) {
        int row = m0 + wm * 64 + mi * 16 + g;
#pragma unroll
        for (int ni = 0; ni < 8; ni++) {
            int col = n0 + wn * 64 + ni * 8 + tig * 2;
            float bx = bias[col], by = bias[col + 1];
            float2 r0 = { acc[mi][ni][0] + bx, acc[mi][ni][1] + by };
            float2 r1 = { acc[mi][ni][2] + bx, acc[mi][ni][3] + by };
            *(float2*)(C + (size_t)row * Dm + col)       = r0;
            *(float2*)(C + (size_t)(row + 8) * Dm + col) = r1;
        }
    }
}

// ---------------------------------------------------------------------------
extern "C" void kernel_launch(void* const* d_in, const int* in_sizes, int n_in,
                              void* d_out, int out_size)
{
    const float* Q    = (const float*)d_in[0];
    const float* K    = (const float*)d_in[1];
    const float* V    = (const float*)d_in[2];
    const float* Wout = (const float*)d_in[3];
    const float* bout = (const float*)d_in[4];
    float* Out = (float*)d_out;

    static bool attr_done = false;
    if (!attr_done) {
        cudaFuncSetAttribute(out_gemm_tc,
                             cudaFuncAttributeMaxDynamicSharedMemorySize, SMEM_DYN);
        attr_done = true;
    }

    kv_q_kernel<<<dim3(BH * KVSPLIT + QBLKS), 256>>>(K, V, Q);
    kv_reduce_kernel<<<dim3(BH * HD * HD / 256), 256>>>();
    w2_kernel<<<dim3(BH, Dm / 128), 128>>>(Wout);
    out_gemm_tc<<<dim3(Sl / TM, Dm / TN, Bsz), 256, SMEM_DYN>>>(bout, Out);
}

// round 12
// speedup vs baseline: 1.1701x; 1.1701x over previous
#include <cuda_runtime.h>
#include <cstdint>

#define Bsz 4
#define Sl 4096
#define Dm 1024
#define Hh 16
#define HD 64
#define BH (Bsz * Hh)
#define KVSPLIT 8

// GEMM-D tiling (round-10 proven config)
#define TM 128
#define TN 128
#define BK 32
#define NS 3
#define NCHUNK (Dm / BK)
#define KPAD 36
#define A_FLOATS (TM * KPAD)
#define B_FLOATS (TN * KPAD)
#define STAGE_FLOATS (A_FLOATS + B_FLOATS)
#define SMEM_DYN (NS * STAGE_FLOATS * 4)   // 110592 B

// Scratch (allocation-free rule: device globals)
__device__ float g_KV_part[16 * BH * HD * HD];
__device__ float g_KV[BH * HD * HD];
__device__ float g_W2[Bsz * Dm * Dm];    // tf32-bit-pattern floats

// ---------------------------------------------------------------------------
// helpers
// ---------------------------------------------------------------------------
__device__ __forceinline__ uint32_t smem_u32(const void* p) {
    uint32_t a;
    asm("{ .reg .u64 t; cvta.to.shared.u64 t, %1; cvt.u32.u64 %0, t; }"
        : "=r"(a) : "l"(p));
    return a;
}
__device__ __forceinline__ void cp16(uint32_t dst, const void* src) {
    asm volatile("cp.async.cg.shared.global [%0], [%1], 16;" :: "r"(dst), "l"(src));
}
__device__ __forceinline__ uint32_t f2tf32(float f) {
    uint32_t r;
    asm("cvt.rna.tf32.f32 %0, %1;" : "=r"(r) : "f"(f));
    return r;
}
__device__ __forceinline__ void ldsm4(uint32_t* d, uint32_t addr) {
    asm volatile("ldmatrix.sync.aligned.m8n8.x4.shared.b16 {%0,%1,%2,%3}, [%4];"
        : "=r"(d[0]), "=r"(d[1]), "=r"(d[2]), "=r"(d[3]) : "r"(addr));
}
__device__ __forceinline__ void mma_tf32_16n8k8(float* c, uint32_t a0, uint32_t a1,
                                                uint32_t a2, uint32_t a3,
                                                uint32_t b0, uint32_t b1) {
    asm volatile(
        "mma.sync.aligned.m16n8k8.row.col.f32.tf32.tf32.f32 "
        "{%0,%1,%2,%3}, {%4,%5,%6,%7}, {%8,%9}, {%0,%1,%2,%3};"
        : "+f"(c[0]), "+f"(c[1]), "+f"(c[2]), "+f"(c[3])
        : "r"(a0), "r"(a1), "r"(a2), "r"(a3), "r"(b0), "r"(b1));
}

// ---------------------------------------------------------------------------
// Kernel A: tensor-core partial KV[b,h,d,e] = sum_s K*V, grid BH*KVSPLIT
// ---------------------------------------------------------------------------
__global__ __launch_bounds__(256) void kv_tc_kernel(
    const float* __restrict__ K, const float* __restrict__ V)
{
    __shared__ float sK[2][16 * 132];
    __shared__ float sV[2][16 * 132];

    const int blk = blockIdx.x;
    const int t   = threadIdx.x;
    const int bh  = blk & (BH - 1);
    const int sp  = blk >> 6;
    const int b = bh >> 4, h = bh & 15;

    const int w   = t >> 5, lid = t & 31;
    const int wg  = w >> 2;
    const int wq  = w & 3;
    const int wm  = wq >> 1;
    const int wn  = wq & 1;
    const int g   = lid >> 2;
    const int tig = lid & 3;

    const float* Kb = K + ((size_t)b * Sl) * Dm + h * HD;
    const float* Vb = V + ((size_t)b * Sl) * Dm + h * HD;
    const int s0 = sp * (Sl / KVSPLIT);

    float acc[2][4][4] = {};

    const int sr = t >> 2;
    const int cg = sr >> 5;
    const int sl = sr & 31;

    for (int it = 0; it < (Sl / KVSPLIT) / 64; it++) {
        size_t grow = (size_t)(s0 + it * 64 + sr) * Dm;
#pragma unroll
        for (int j = 0; j < 4; j++) {
            int db = (t & 3) + j * 4;
            float4 kv = *(const float4*)(Kb + grow + db * 4);
            float4 vv = *(const float4*)(Vb + grow + db * 4);
            float4 ko, vo;
            ko.x = __uint_as_float(f2tf32(kv.x));
            ko.y = __uint_as_float(f2tf32(kv.y));
            ko.z = __uint_as_float(f2tf32(kv.z));
            ko.w = __uint_as_float(f2tf32(kv.w));
            vo.x = __uint_as_float(f2tf32(vv.x));
            vo.y = __uint_as_float(f2tf32(vv.y));
            vo.z = __uint_as_float(f2tf32(vv.z));
            vo.w = __uint_as_float(f2tf32(vv.w));
            *(float4*)&sK[cg][db * 132 + sl * 4] = ko;
            *(float4*)&sV[cg][db * 132 + sl * 4] = vo;
        }
        __syncthreads();

        const float* Kt = sK[wg];
        const float* Vt = sV[wg];
#pragma unroll
        for (int ks = 0; ks < 4; ks++) {
            const int k0 = ks * 8;
            uint32_t a[2][4];
#pragma unroll
            for (int mi = 0; mi < 2; mi++) {
                int d = wm * 32 + mi * 16 + g;
                int i0 = (d >> 2) * 132 + (k0 + tig) * 4 + (d & 3);
                a[mi][0] = __float_as_uint(Kt[i0]);
                a[mi][1] = __float_as_uint(Kt[i0 + 264]);
                a[mi][2] = __float_as_uint(Kt[i0 + 16]);
                a[mi][3] = __float_as_uint(Kt[i0 + 280]);
            }
#pragma unroll
            for (int ni = 0; ni < 4; ni++) {
                int e = wn * 32 + ni * 8 + g;
                int i0 = (e >> 2) * 132 + (k0 + tig) * 4 + (e & 3);
                uint32_t b0 = __float_as_uint(Vt[i0]);
                uint32_t b1 = __float_as_uint(Vt[i0 + 16]);
#pragma unroll
                for (int mi = 0; mi < 2; mi++)
                    mma_tf32_16n8k8(acc[mi][ni],
                                    a[mi][0], a[mi][1], a[mi][2], a[mi][3],
                                    b0, b1);
            }
        }
        __syncthreads();
    }

    float* out = g_KV_part + ((size_t)(sp * 2 + wg) * BH + bh) * (HD * HD);
#pragma unroll
    for (int mi = 0; mi < 2; mi++) {
        int d = wm * 32 + mi * 16 + g;
#pragma unroll
        for (int ni = 0; ni < 4; ni++) {
            int e = wn * 32 + ni * 8 + tig * 2;
            *(float2*)(out + d * HD + e)       = make_float2(acc[mi][ni][0], acc[mi][ni][1]);
            *(float2*)(out + (d + 8) * HD + e) = make_float2(acc[mi][ni][2], acc[mi][ni][3]);
        }
    }
}

// ---------------------------------------------------------------------------
// Kernel B: deterministic reduction of 16 partials
// ---------------------------------------------------------------------------
__global__ __launch_bounds__(256) void kv_reduce_kernel()
{
    int idx = blockIdx.x * 256 + threadIdx.x;
    float s = 0.f;
#pragma unroll
    for (int p = 0; p < 16; p++)
        s += g_KV_part[(size_t)p * (BH * HD * HD) + idx];
    g_KV[idx] = s;
}

// ---------------------------------------------------------------------------
// Kernel C: W2[b][o][h*64+d] = sum_e KV[b,h,d,e] * W[o*Dm + h*64 + e]
// Stores tf32 bit patterns (kernel D's B operand).
// ---------------------------------------------------------------------------
__global__ __launch_bounds__(128) void w2_kernel(const float* __restrict__ W)
{
    __shared__ float KVt[64][64];
    __shared__ float WsT[64][128];

    const int bh = blockIdx.x;
    const int b = bh >> 4, h = bh & 15;
    const int t = threadIdx.x;
    const int o_base = blockIdx.y * 128;

#pragma unroll
    for (int i = 0; i < 8; i++) {
        int idx = t + i * 128;
        int rd = idx & 63;
        int c4 = (idx >> 6) * 4;
        float4 v = *(const float4*)(g_KV + (size_t)bh * 4096 + rd * 64 + c4);
        KVt[c4 + 0][rd] = v.x; KVt[c4 + 1][rd] = v.y;
        KVt[c4 + 2][rd] = v.z; KVt[c4 + 3][rd] = v.w;
    }
#pragma unroll
    for (int i = 0; i < 16; i++) {
        int idx = t + i * 128;
        int ro = idx & 127;
        int c4 = (idx >> 7) * 4;
        float4 v = *(const float4*)(W + (size_t)(o_base + ro) * Dm + h * HD + c4);
        WsT[c4 + 0][ro] = v.x; WsT[c4 + 1][ro] = v.y;
        WsT[c4 + 2][ro] = v.z; WsT[c4 + 3][ro] = v.w;
    }
    __syncthreads();

    const int d0 = (t & 7) * 8;
    const int o0 = (t >> 3) * 8;
    float acc[8][8] = {};
#pragma unroll 4
    for (int e = 0; e < 64; e++) {
        float ww[8], kk[8];
        *(float4*)&ww[0] = *(const float4*)&WsT[e][o0];
        *(float4*)&ww[4] = *(const float4*)&WsT[e][o0 + 4];
        *(float4*)&kk[0] = *(const float4*)&KVt[e][d0];
        *(float4*)&kk[4] = *(const float4*)&KVt[e][d0 + 4];
#pragma unroll
        for (int i = 0; i < 8; i++)
#pragma unroll
            for (int j = 0; j < 8; j++)
                acc[i][j] += ww[i] * kk[j];
    }

#pragma unroll
    for (int i = 0; i < 8; i++) {
        float* dst = g_W2 + ((size_t)b * Dm + (o_base + o0 + i)) * Dm + h * HD + d0;
#pragma unroll
        for (int jj = 0; jj < 2; jj++) {
            float4 o;
            o.x = __uint_as_float(f2tf32(acc[i][jj * 4 + 0]));
            o.y = __uint_as_float(f2tf32(acc[i][jj * 4 + 1]));
            o.z = __uint_as_float(f2tf32(acc[i][jj * 4 + 2]));
            o.w = __uint_as_float(f2tf32(acc[i][jj * 4 + 3]));
            *(float4*)(dst + jj * 4) = o;
        }
    }
}

// ---------------------------------------------------------------------------
// Kernel D: out[b,m,n] = sum_k Q[b,m,k]*W2[b,n,k] + bias[n]
// Round-10 config (CTA 128x128, warp 64x32, NS=3, 2 CTAs/SM), but A is
// converted inline in the producer path: LDG.128 Q -> cvt.rna -> STS.128.
// B stays cp.async (pre-converted tf32 bits from w2). No Qtf round-trip.
// ---------------------------------------------------------------------------
__global__ __launch_bounds__(256, 2) void out_gemm_tc(
    const float* __restrict__ Q, const float* __restrict__ bias,
    float* __restrict__ Out)
{
    extern __shared__ float smem[];

    const int t   = threadIdx.x;
    const int wid = t >> 5;
    const int lid = t & 31;
    const int g   = lid >> 2;
    const int tig = lid & 3;
    const int wm  = wid >> 2;
    const int wn  = wid & 3;

    const int m0 = blockIdx.x * TM;
    const int n0 = blockIdx.y * TN;
    const int b  = blockIdx.z;

    const float* Ag = Q    + (size_t)b * Sl * Dm + (size_t)m0 * Dm;
    const float* Bg = g_W2 + (size_t)b * Dm * Dm + (size_t)n0 * Dm;

    const uint32_t u0 = smem_u32(smem);

    // B: cp.async (async-pipelined). A: LDG -> cvt.rna -> STS (producer path).
    auto load_B = [&](int s, int k0) {
        uint32_t uB = u0 + (uint32_t)(s * STAGE_FLOATS + A_FLOATS) * 4;
#pragma unroll
        for (int i = 0; i < 4; i++) {
            int idx = t + (i << 8);
            int row = idx >> 3, c = idx & 7;
            cp16(uB + row * (KPAD * 4) + c * 16, Bg + (size_t)row * Dm + k0 + c * 4);
        }
    };
    auto load_A = [&](int s, int k0) {
        uint32_t uA = u0 + (uint32_t)(s * STAGE_FLOATS) * 4;
#pragma unroll
        for (int i = 0; i < 4; i++) {
            int idx = t + (i << 8);
            int row = idx >> 3, c = idx & 7;
            float4 v = *(const float4*)(Ag + (size_t)row * Dm + k0 + c * 4);
            uint4 o;
            o.x = f2tf32(v.x); o.y = f2tf32(v.y);
            o.z = f2tf32(v.z); o.w = f2tf32(v.w);
            *(uint4*)(smem + (size_t)s * STAGE_FLOATS + row * KPAD + c * 4) = o;
            (void)uA;
        }
    };

    float acc[4][4][4] = {};

    load_B(0, 0);
    asm volatile("cp.async.commit_group;" ::: "memory");
    load_B(1, BK);
    asm volatile("cp.async.commit_group;" ::: "memory");
    load_A(0, 0);
    load_A(1, BK);

    const uint32_t aBase = (uint32_t)(wm * 64 + (lid & 15)) * (KPAD * 4)
                         + (uint32_t)(lid >> 4) * 16;
    const uint32_t bBase = (uint32_t)(wn * 32 + ((lid >> 4) << 3) + (lid & 7)) * (KPAD * 4)
                         + (uint32_t)((lid >> 3) & 1) * 16;

    int s = 0;
    for (int i = 0; i < NCHUNK; i++) {
        asm volatile("cp.async.wait_group 1;" ::: "memory");
        __syncthreads();

        if (i + 2 < NCHUNK) {
            int sn = s + 2; if (sn >= NS) sn -= NS;
            load_B(sn, (i + 2) * BK);
            asm volatile("cp.async.commit_group;" ::: "memory");
            load_A(sn, (i + 2) * BK);
        } else {
            asm volatile("cp.async.commit_group;" ::: "memory");
        }

        uint32_t uA = u0 + (uint32_t)(s * STAGE_FLOATS) * 4;
        uint32_t uB = uA + A_FLOATS * 4;

#pragma unroll
        for (int ks = 0; ks < 4; ks++) {
            uint32_t af[4][4];
#pragma unroll
            for (int mi = 0; mi < 4; mi++)
                ldsm4(af[mi], uA + aBase + mi * 16 * (KPAD * 4) + ks * 32);
            uint32_t bf[2][4];
#pragma unroll
            for (int p = 0; p < 2; p++)
                ldsm4(bf[p], uB + bBase + p * 16 * (KPAD * 4) + ks * 32);
#pragma unroll
            for (int mi = 0; mi < 4; mi++)
#pragma unroll
                for (int ni = 0; ni < 4; ni++) {
                    const int p = ni >> 1, q = (ni & 1) * 2;
                    mma_tf32_16n8k8(acc[mi][ni],
                                    af[mi][0], af[mi][1], af[mi][2], af[mi][3],
                                    bf[p][q], bf[p][q + 1]);
                }
        }
        if (++s == NS) s = 0;
    }

    float* C = Out + (size_t)b * Sl * Dm;
#pragma unroll
    for (int mi = 0; mi < 4; mi++) {
        int row = m0 + wm * 64 + mi * 16 + g;
#pragma unroll
        for (int ni = 0; ni < 4; ni++) {
            int col = n0 + wn * 32 + ni * 8 + tig * 2;
            float bx = bias[col], by = bias[col + 1];
            float2 r0 = { acc[mi][ni][0] + bx, acc[mi][ni][1] + by };
            float2 r1 = { acc[mi][ni][2] + bx, acc[mi][ni][3] + by };
            *(float2*)(C + (size_t)row * Dm + col)       = r0;
            *(float2*)(C + (size_t)(row + 8) * Dm + col) = r1;
        }
    }
}

// ---------------------------------------------------------------------------
extern "C" void kernel_launch(void* const* d_in, const int* in_sizes, int n_in,
                              void* d_out, int out_size)
{
    const float* Q    = (const float*)d_in[0];
    const float* K    = (const float*)d_in[1];
    const float* V    = (const float*)d_in[2];
    const float* Wout = (const float*)d_in[3];
    const float* bout = (const float*)d_in[4];
    float* Out = (float*)d_out;

    static bool attr_done = false;
    if (!attr_done) {
        cudaFuncSetAttribute(out_gemm_tc,
                             cudaFuncAttributeMaxDynamicSharedMemorySize, SMEM_DYN);
        attr_done = true;
    }

    kv_tc_kernel<<<dim3(BH * KVSPLIT), 256>>>(K, V);
    kv_reduce_kernel<<<dim3(BH * HD * HD / 256), 256>>>();
    w2_kernel<<<dim3(BH, Dm / 128), 128>>>(Wout);
    out_gemm_tc<<<dim3(Sl / TM, Dm / TN, Bsz), 256, SMEM_DYN>>>(Q, bout, Out);
}

// round 13
// speedup vs baseline: 1.2170x; 1.0400x over previous
#include <cuda_runtime.h>
#include <cstdint>

#define Bsz 4
#define Sl 4096
#define Dm 1024
#define Hh 16
#define HD 64
#define BH (Bsz * Hh)
#define KVSPLIT 8

// GEMM-D tiling (round-10 proven config)
#define TM 128
#define TN 128
#define BK 32
#define NS 3
#define NCHUNK (Dm / BK)
#define KPAD 36
#define A_FLOATS (TM * KPAD)
#define B_FLOATS (TN * KPAD)
#define STAGE_FLOATS (A_FLOATS + B_FLOATS)
#define SMEM_DYN (NS * STAGE_FLOATS * 4)   // 110592 B

// Scratch (allocation-free rule: device globals)
__device__ float g_KV_part[16 * BH * HD * HD];
__device__ float g_KV[BH * HD * HD];
__device__ float g_W2[Bsz * Dm * Dm];    // tf32-bit-pattern floats

// ---------------------------------------------------------------------------
// helpers
// ---------------------------------------------------------------------------
__device__ __forceinline__ uint32_t smem_u32(const void* p) {
    uint32_t a;
    asm("{ .reg .u64 t; cvta.to.shared.u64 t, %1; cvt.u32.u64 %0, t; }"
        : "=r"(a) : "l"(p));
    return a;
}
__device__ __forceinline__ void cp16(uint32_t dst, const void* src) {
    asm volatile("cp.async.cg.shared.global [%0], [%1], 16;" :: "r"(dst), "l"(src));
}
__device__ __forceinline__ uint32_t f2tf32(float f) {
    uint32_t r;
    asm("cvt.rna.tf32.f32 %0, %1;" : "=r"(r) : "f"(f));
    return r;
}
__device__ __forceinline__ void ldsm4(uint32_t* d, uint32_t addr) {
    asm volatile("ldmatrix.sync.aligned.m8n8.x4.shared.b16 {%0,%1,%2,%3}, [%4];"
        : "=r"(d[0]), "=r"(d[1]), "=r"(d[2]), "=r"(d[3]) : "r"(addr));
}
__device__ __forceinline__ void mma_tf32_16n8k8(float* c, uint32_t a0, uint32_t a1,
                                                uint32_t a2, uint32_t a3,
                                                uint32_t b0, uint32_t b1) {
    asm volatile(
        "mma.sync.aligned.m16n8k8.row.col.f32.tf32.tf32.f32 "
        "{%0,%1,%2,%3}, {%4,%5,%6,%7}, {%8,%9}, {%0,%1,%2,%3};"
        : "+f"(c[0]), "+f"(c[1]), "+f"(c[2]), "+f"(c[3])
        : "r"(a0), "r"(a1), "r"(a2), "r"(a3), "r"(b0), "r"(b1));
}

// ---------------------------------------------------------------------------
// Kernel A: tensor-core partial KV[b,h,d,e] = sum_s K*V, grid BH*KVSPLIT
// ---------------------------------------------------------------------------
__global__ __launch_bounds__(256) void kv_tc_kernel(
    const float* __restrict__ K, const float* __restrict__ V)
{
    __shared__ float sK[2][16 * 132];
    __shared__ float sV[2][16 * 132];

    const int blk = blockIdx.x;
    const int t   = threadIdx.x;
    const int bh  = blk & (BH - 1);
    const int sp  = blk >> 6;
    const int b = bh >> 4, h = bh & 15;

    const int w   = t >> 5, lid = t & 31;
    const int wg  = w >> 2;
    const int wq  = w & 3;
    const int wm  = wq >> 1;
    const int wn  = wq & 1;
    const int g   = lid >> 2;
    const int tig = lid & 3;

    const float* Kb = K + ((size_t)b * Sl) * Dm + h * HD;
    const float* Vb = V + ((size_t)b * Sl) * Dm + h * HD;
    const int s0 = sp * (Sl / KVSPLIT);

    float acc[2][4][4] = {};

    const int sr = t >> 2;
    const int cg = sr >> 5;
    const int sl = sr & 31;

    for (int it = 0; it < (Sl / KVSPLIT) / 64; it++) {
        size_t grow = (size_t)(s0 + it * 64 + sr) * Dm;
#pragma unroll
        for (int j = 0; j < 4; j++) {
            int db = (t & 3) + j * 4;
            float4 kv = *(const float4*)(Kb + grow + db * 4);
            float4 vv = *(const float4*)(Vb + grow + db * 4);
            float4 ko, vo;
            ko.x = __uint_as_float(f2tf32(kv.x));
            ko.y = __uint_as_float(f2tf32(kv.y));
            ko.z = __uint_as_float(f2tf32(kv.z));
            ko.w = __uint_as_float(f2tf32(kv.w));
            vo.x = __uint_as_float(f2tf32(vv.x));
            vo.y = __uint_as_float(f2tf32(vv.y));
            vo.z = __uint_as_float(f2tf32(vv.z));
            vo.w = __uint_as_float(f2tf32(vv.w));
            *(float4*)&sK[cg][db * 132 + sl * 4] = ko;
            *(float4*)&sV[cg][db * 132 + sl * 4] = vo;
        }
        __syncthreads();

        const float* Kt = sK[wg];
        const float* Vt = sV[wg];
#pragma unroll
        for (int ks = 0; ks < 4; ks++) {
            const int k0 = ks * 8;
            uint32_t a[2][4];
#pragma unroll
            for (int mi = 0; mi < 2; mi++) {
                int d = wm * 32 + mi * 16 + g;
                int i0 = (d >> 2) * 132 + (k0 + tig) * 4 + (d & 3);
                a[mi][0] = __float_as_uint(Kt[i0]);
                a[mi][1] = __float_as_uint(Kt[i0 + 264]);
                a[mi][2] = __float_as_uint(Kt[i0 + 16]);
                a[mi][3] = __float_as_uint(Kt[i0 + 280]);
            }
#pragma unroll
            for (int ni = 0; ni < 4; ni++) {
                int e = wn * 32 + ni * 8 + g;
                int i0 = (e >> 2) * 132 + (k0 + tig) * 4 + (e & 3);
                uint32_t b0 = __float_as_uint(Vt[i0]);
                uint32_t b1 = __float_as_uint(Vt[i0 + 16]);
#pragma unroll
                for (int mi = 0; mi < 2; mi++)
                    mma_tf32_16n8k8(acc[mi][ni],
                                    a[mi][0], a[mi][1], a[mi][2], a[mi][3],
                                    b0, b1);
            }
        }
        __syncthreads();
    }

    float* out = g_KV_part + ((size_t)(sp * 2 + wg) * BH + bh) * (HD * HD);
#pragma unroll
    for (int mi = 0; mi < 2; mi++) {
        int d = wm * 32 + mi * 16 + g;
#pragma unroll
        for (int ni = 0; ni < 4; ni++) {
            int e = wn * 32 + ni * 8 + tig * 2;
            *(float2*)(out + d * HD + e)       = make_float2(acc[mi][ni][0], acc[mi][ni][1]);
            *(float2*)(out + (d + 8) * HD + e) = make_float2(acc[mi][ni][2], acc[mi][ni][3]);
        }
    }
}

// ---------------------------------------------------------------------------
// Kernel B: deterministic reduction of 16 partials
// ---------------------------------------------------------------------------
__global__ __launch_bounds__(256) void kv_reduce_kernel()
{
    int idx = blockIdx.x * 256 + threadIdx.x;
    float s = 0.f;
#pragma unroll
    for (int p = 0; p < 16; p++)
        s += g_KV_part[(size_t)p * (BH * HD * HD) + idx];
    g_KV[idx] = s;
}

// ---------------------------------------------------------------------------
// Kernel C: W2[b][o][h*64+d] = sum_e KV[b,h,d,e] * W[o*Dm + h*64 + e]
// Stores tf32 bit patterns (kernel D's B operand, RNA-rounded).
// ---------------------------------------------------------------------------
__global__ __launch_bounds__(128) void w2_kernel(const float* __restrict__ W)
{
    __shared__ float KVt[64][64];
    __shared__ float WsT[64][128];

    const int bh = blockIdx.x;
    const int b = bh >> 4, h = bh & 15;
    const int t = threadIdx.x;
    const int o_base = blockIdx.y * 128;

#pragma unroll
    for (int i = 0; i < 8; i++) {
        int idx = t + i * 128;
        int rd = idx & 63;
        int c4 = (idx >> 6) * 4;
        float4 v = *(const float4*)(g_KV + (size_t)bh * 4096 + rd * 64 + c4);
        KVt[c4 + 0][rd] = v.x; KVt[c4 + 1][rd] = v.y;
        KVt[c4 + 2][rd] = v.z; KVt[c4 + 3][rd] = v.w;
    }
#pragma unroll
    for (int i = 0; i < 16; i++) {
        int idx = t + i * 128;
        int ro = idx & 127;
        int c4 = (idx >> 7) * 4;
        float4 v = *(const float4*)(W + (size_t)(o_base + ro) * Dm + h * HD + c4);
        WsT[c4 + 0][ro] = v.x; WsT[c4 + 1][ro] = v.y;
        WsT[c4 + 2][ro] = v.z; WsT[c4 + 3][ro] = v.w;
    }
    __syncthreads();

    const int d0 = (t & 7) * 8;
    const int o0 = (t >> 3) * 8;
    float acc[8][8] = {};
#pragma unroll 4
    for (int e = 0; e < 64; e++) {
        float ww[8], kk[8];
        *(float4*)&ww[0] = *(const float4*)&WsT[e][o0];
        *(float4*)&ww[4] = *(const float4*)&WsT[e][o0 + 4];
        *(float4*)&kk[0] = *(const float4*)&KVt[e][d0];
        *(float4*)&kk[4] = *(const float4*)&KVt[e][d0 + 4];
#pragma unroll
        for (int i = 0; i < 8; i++)
#pragma unroll
            for (int j = 0; j < 8; j++)
                acc[i][j] += ww[i] * kk[j];
    }

#pragma unroll
    for (int i = 0; i < 8; i++) {
        float* dst = g_W2 + ((size_t)b * Dm + (o_base + o0 + i)) * Dm + h * HD + d0;
#pragma unroll
        for (int jj = 0; jj < 2; jj++) {
            float4 o;
            o.x = __uint_as_float(f2tf32(acc[i][jj * 4 + 0]));
            o.y = __uint_as_float(f2tf32(acc[i][jj * 4 + 1]));
            o.z = __uint_as_float(f2tf32(acc[i][jj * 4 + 2]));
            o.w = __uint_as_float(f2tf32(acc[i][jj * 4 + 3]));
            *(float4*)(dst + jj * 4) = o;
        }
    }
}

// ---------------------------------------------------------------------------
// Kernel D: out[b,m,n] = sum_k Q[b,m,k]*W2[b,n,k] + bias[n]
// Round-10 config (CTA 128x128, warp 64x32, NS=3, 2 CTAs/SM), both operands
// via cp.async + ldmatrix. A = RAW fp32 Q bits: tf32 mma reads only the top
// 19 bits (implicit RZ truncation) -> no conversion pass, no Qtf buffer.
// B = RNA tf32 bits from w2.
// ---------------------------------------------------------------------------
__global__ __launch_bounds__(256, 2) void out_gemm_tc(
    const float* __restrict__ Q, const float* __restrict__ bias,
    float* __restrict__ Out)
{
    extern __shared__ float smem[];

    const int t   = threadIdx.x;
    const int wid = t >> 5;
    const int lid = t & 31;
    const int g   = lid >> 2;
    const int tig = lid & 3;
    const int wm  = wid >> 2;
    const int wn  = wid & 3;

    const int m0 = blockIdx.x * TM;
    const int n0 = blockIdx.y * TN;
    const int b  = blockIdx.z;

    const float* Ag = Q    + (size_t)b * Sl * Dm + (size_t)m0 * Dm;
    const float* Bg = g_W2 + (size_t)b * Dm * Dm + (size_t)n0 * Dm;

    const uint32_t u0 = smem_u32(smem);

    auto load_stage = [&](int s, int k0) {
        uint32_t uA = u0 + (uint32_t)(s * STAGE_FLOATS) * 4;
        uint32_t uB = uA + A_FLOATS * 4;
#pragma unroll
        for (int i = 0; i < 4; i++) {
            int idx = t + (i << 8);
            int row = idx >> 3, c = idx & 7;
            cp16(uA + row * (KPAD * 4) + c * 16, Ag + (size_t)row * Dm + k0 + c * 4);
        }
#pragma unroll
        for (int i = 0; i < 4; i++) {
            int idx = t + (i << 8);
            int row = idx >> 3, c = idx & 7;
            cp16(uB + row * (KPAD * 4) + c * 16, Bg + (size_t)row * Dm + k0 + c * 4);
        }
    };

    float acc[4][4][4] = {};

    load_stage(0, 0);
    asm volatile("cp.async.commit_group;" ::: "memory");
    load_stage(1, BK);
    asm volatile("cp.async.commit_group;" ::: "memory");

    const uint32_t aBase = (uint32_t)(wm * 64 + (lid & 15)) * (KPAD * 4)
                         + (uint32_t)(lid >> 4) * 16;
    const uint32_t bBase = (uint32_t)(wn * 32 + ((lid >> 4) << 3) + (lid & 7)) * (KPAD * 4)
                         + (uint32_t)((lid >> 3) & 1) * 16;

    int s = 0;
    for (int i = 0; i < NCHUNK; i++) {
        asm volatile("cp.async.wait_group 1;" ::: "memory");
        __syncthreads();

        if (i + 2 < NCHUNK) {
            int sn = s + 2; if (sn >= NS) sn -= NS;
            load_stage(sn, (i + 2) * BK);
        }
        asm volatile("cp.async.commit_group;" ::: "memory");

        uint32_t uA = u0 + (uint32_t)(s * STAGE_FLOATS) * 4;
        uint32_t uB = uA + A_FLOATS * 4;

#pragma unroll
        for (int ks = 0; ks < 4; ks++) {
            uint32_t af[4][4];
#pragma unroll
            for (int mi = 0; mi < 4; mi++)
                ldsm4(af[mi], uA + aBase + mi * 16 * (KPAD * 4) + ks * 32);
            uint32_t bf[2][4];
#pragma unroll
            for (int p = 0; p < 2; p++)
                ldsm4(bf[p], uB + bBase + p * 16 * (KPAD * 4) + ks * 32);
#pragma unroll
            for (int mi = 0; mi < 4; mi++)
#pragma unroll
                for (int ni = 0; ni < 4; ni++) {
                    const int p = ni >> 1, q = (ni & 1) * 2;
                    mma_tf32_16n8k8(acc[mi][ni],
                                    af[mi][0], af[mi][1], af[mi][2], af[mi][3],
                                    bf[p][q], bf[p][q + 1]);
                }
        }
        if (++s == NS) s = 0;
    }

    float* C = Out + (size_t)b * Sl * Dm;
#pragma unroll
    for (int mi = 0; mi < 4; mi++) {
        int row = m0 + wm * 64 + mi * 16 + g;
#pragma unroll
        for (int ni = 0; ni < 4; ni++) {
            int col = n0 + wn * 32 + ni * 8 + tig * 2;
            float bx = bias[col], by = bias[col + 1];
            float2 r0 = { acc[mi][ni][0] + bx, acc[mi][ni][1] + by };
            float2 r1 = { acc[mi][ni][2] + bx, acc[mi][ni][3] + by };
            *(float2*)(C + (size_t)row * Dm + col)       = r0;
            *(float2*)(C + (size_t)(row + 8) * Dm + col) = r1;
        }
    }
}

// ---------------------------------------------------------------------------
extern "C" void kernel_launch(void* const* d_in, const int* in_sizes, int n_in,
                              void* d_out, int out_size)
{
    const float* Q    = (const float*)d_in[0];
    const float* K    = (const float*)d_in[1];
    const float* V    = (const float*)d_in[2];
    const float* Wout = (const float*)d_in[3];
    const float* bout = (const float*)d_in[4];
    float* Out = (float*)d_out;

    static bool attr_done = false;
    if (!attr_done) {
        cudaFuncSetAttribute(out_gemm_tc,
                             cudaFuncAttributeMaxDynamicSharedMemorySize, SMEM_DYN);
        attr_done = true;
    }

    kv_tc_kernel<<<dim3(BH * KVSPLIT), 256>>>(K, V);
    kv_reduce_kernel<<<dim3(BH * HD * HD / 256), 256>>>();
    w2_kernel<<<dim3(BH, Dm / 128), 128>>>(Wout);
    out_gemm_tc<<<dim3(Sl / TM, Dm / TN, Bsz), 256, SMEM_DYN>>>(Q, bout, Out);
}

// round 16
// speedup vs baseline: 1.3201x; 1.0848x over previous
#include <cuda_runtime.h>
#include <cstdint>

#define Bsz 4
#define Sl 4096
#define Dm 1024
#define Hh 16
#define HD 64
#define BH (Bsz * Hh)
#define KVSPLIT 8

// GEMM-D tiling
#define TM 128
#define TN 128
#define BK 32
#define NS 3
#define NCHUNK (Dm / BK)
#define KPAD 36
#define A_FLOATS (TM * KPAD)
#define B_FLOATS (TN * KPAD)
#define STAGE_FLOATS (A_FLOATS + B_FLOATS)
#define SMEM_DYN (NS * STAGE_FLOATS * 4)   // 110592 B

// Scratch (allocation-free rule: device globals)
__device__ float g_KV_part[16 * BH * HD * HD];
__device__ float g_KV[BH * HD * HD];
__device__ float g_W2[Bsz * Dm * Dm];    // tf32-bit-pattern floats

// ---------------------------------------------------------------------------
// helpers
// ---------------------------------------------------------------------------
__device__ __forceinline__ uint32_t smem_u32(const void* p) {
    uint32_t a;
    asm("{ .reg .u64 t; cvta.to.shared.u64 t, %1; cvt.u32.u64 %0, t; }"
        : "=r"(a) : "l"(p));
    return a;
}
__device__ __forceinline__ void cp16(uint32_t dst, const void* src) {
    asm volatile("cp.async.cg.shared.global [%0], [%1], 16;" :: "r"(dst), "l"(src));
}
__device__ __forceinline__ uint32_t f2tf32(float f) {
    uint32_t r;
    asm("cvt.rna.tf32.f32 %0, %1;" : "=r"(r) : "f"(f));
    return r;
}
__device__ __forceinline__ void ldsm4(uint32_t* d, uint32_t addr) {
    asm volatile("ldmatrix.sync.aligned.m8n8.x4.shared.b16 {%0,%1,%2,%3}, [%4];"
        : "=r"(d[0]), "=r"(d[1]), "=r"(d[2]), "=r"(d[3]) : "r"(addr));
}
__device__ __forceinline__ void mma_tf32_16n8k8(float* c, uint32_t a0, uint32_t a1,
                                                uint32_t a2, uint32_t a3,
                                                uint32_t b0, uint32_t b1) {
    asm volatile(
        "mma.sync.aligned.m16n8k8.row.col.f32.tf32.tf32.f32 "
        "{%0,%1,%2,%3}, {%4,%5,%6,%7}, {%8,%9}, {%0,%1,%2,%3};"
        : "+f"(c[0]), "+f"(c[1]), "+f"(c[2]), "+f"(c[3])
        : "r"(a0), "r"(a1), "r"(a2), "r"(a3), "r"(b0), "r"(b1));
}

#define MBAR_INIT(a, n) \
    asm volatile("mbarrier.init.shared.b64 [%0], %1;" :: "r"(a), "r"((uint32_t)(n)) : "memory")
#define MBAR_ARRIVE(a) \
    asm volatile("mbarrier.arrive.shared.b64 _, [%0];" :: "r"(a) : "memory")
// .noinc is load-bearing: the plain form increments pending count at issue and
// cancels it at completion (net zero -> deadlock against a fixed init count).
#define CPASYNC_MBAR_ARRIVE(a) \
    asm volatile("cp.async.mbarrier.arrive.noinc.shared.b64 [%0];" :: "r"(a) : "memory")
#define MBAR_WAIT(a, par) do {                                                     \
    uint32_t _m = (a), _p = (par), _d;                                             \
    asm volatile("{\n\t.reg .pred p;\n\t"                                          \
        "mbarrier.try_wait.parity.acquire.cta.shared::cta.b64 p, [%1], %2;\n\t"    \
        "selp.b32 %0, 1, 0, p;\n\t}"                                               \
        : "=r"(_d) : "r"(_m), "r"(_p) : "memory");                                 \
    if (!_d) {                                                                     \
        asm volatile("{\n\t.reg .pred P1;\n\t"                                     \
            "W%=:\n\t"                                                             \
            "mbarrier.try_wait.parity.acquire.cta.shared::cta.b64 P1, [%0], %1, 0x989680;\n\t" \
            "@P1 bra.uni D%=;\n\t bra.uni W%=;\n\t D%=:\n\t}"                      \
            :: "r"(_m), "r"(_p) : "memory");                                       \
    }                                                                              \
} while (0)

// ---------------------------------------------------------------------------
// Kernel A: tensor-core partial KV[b,h,d,e] = sum_s K*V, grid BH*KVSPLIT
// ---------------------------------------------------------------------------
__global__ __launch_bounds__(256) void kv_tc_kernel(
    const float* __restrict__ K, const float* __restrict__ V)
{
    __shared__ float sK[2][16 * 132];
    __shared__ float sV[2][16 * 132];

    const int blk = blockIdx.x;
    const int t   = threadIdx.x;
    const int bh  = blk & (BH - 1);
    const int sp  = blk >> 6;
    const int b = bh >> 4, h = bh & 15;

    const int w   = t >> 5, lid = t & 31;
    const int wg  = w >> 2;
    const int wq  = w & 3;
    const int wm  = wq >> 1;
    const int wn  = wq & 1;
    const int g   = lid >> 2;
    const int tig = lid & 3;

    const float* Kb = K + ((size_t)b * Sl) * Dm + h * HD;
    const float* Vb = V + ((size_t)b * Sl) * Dm + h * HD;
    const int s0 = sp * (Sl / KVSPLIT);

    float acc[2][4][4] = {};

    const int sr = t >> 2;
    const int cg = sr >> 5;
    const int sl = sr & 31;

    for (int it = 0; it < (Sl / KVSPLIT) / 64; it++) {
        size_t grow = (size_t)(s0 + it * 64 + sr) * Dm;
#pragma unroll
        for (int j = 0; j < 4; j++) {
            int db = (t & 3) + j * 4;
            float4 kv = *(const float4*)(Kb + grow + db * 4);
            float4 vv = *(const float4*)(Vb + grow + db * 4);
            float4 ko, vo;
            ko.x = __uint_as_float(f2tf32(kv.x));
            ko.y = __uint_as_float(f2tf32(kv.y));
            ko.z = __uint_as_float(f2tf32(kv.z));
            ko.w = __uint_as_float(f2tf32(kv.w));
            vo.x = __uint_as_float(f2tf32(vv.x));
            vo.y = __uint_as_float(f2tf32(vv.y));
            vo.z = __uint_as_float(f2tf32(vv.z));
            vo.w = __uint_as_float(f2tf32(vv.w));
            *(float4*)&sK[cg][db * 132 + sl * 4] = ko;
            *(float4*)&sV[cg][db * 132 + sl * 4] = vo;
        }
        __syncthreads();

        const float* Kt = sK[wg];
        const float* Vt = sV[wg];
#pragma unroll
        for (int ks = 0; ks < 4; ks++) {
            const int k0 = ks * 8;
            uint32_t a[2][4];
#pragma unroll
            for (int mi = 0; mi < 2; mi++) {
                int d = wm * 32 + mi * 16 + g;
                int i0 = (d >> 2) * 132 + (k0 + tig) * 4 + (d & 3);
                a[mi][0] = __float_as_uint(Kt[i0]);
                a[mi][1] = __float_as_uint(Kt[i0 + 264]);
                a[mi][2] = __float_as_uint(Kt[i0 + 16]);
                a[mi][3] = __float_as_uint(Kt[i0 + 280]);
            }
#pragma unroll
            for (int ni = 0; ni < 4; ni++) {
                int e = wn * 32 + ni * 8 + g;
                int i0 = (e >> 2) * 132 + (k0 + tig) * 4 + (e & 3);
                uint32_t b0 = __float_as_uint(Vt[i0]);
                uint32_t b1 = __float_as_uint(Vt[i0 + 16]);
#pragma unroll
                for (int mi = 0; mi < 2; mi++)
                    mma_tf32_16n8k8(acc[mi][ni],
                                    a[mi][0], a[mi][1], a[mi][2], a[mi][3],
                                    b0, b1);
            }
        }
        __syncthreads();
    }

    float* out = g_KV_part + ((size_t)(sp * 2 + wg) * BH + bh) * (HD * HD);
#pragma unroll
    for (int mi = 0; mi < 2; mi++) {
        int d = wm * 32 + mi * 16 + g;
#pragma unroll
        for (int ni = 0; ni < 4; ni++) {
            int e = wn * 32 + ni * 8 + tig * 2;
            *(float2*)(out + d * HD + e)       = make_float2(acc[mi][ni][0], acc[mi][ni][1]);
            *(float2*)(out + (d + 8) * HD + e) = make_float2(acc[mi][ni][2], acc[mi][ni][3]);
        }
    }
}

// ---------------------------------------------------------------------------
// Kernel B: deterministic reduction of 16 partials
// ---------------------------------------------------------------------------
__global__ __launch_bounds__(256) void kv_reduce_kernel()
{
    int idx = blockIdx.x * 256 + threadIdx.x;
    float s = 0.f;
#pragma unroll
    for (int p = 0; p < 16; p++)
        s += g_KV_part[(size_t)p * (BH * HD * HD) + idx];
    g_KV[idx] = s;
}

// ---------------------------------------------------------------------------
// Kernel C: W2[b][o][h*64+d] = sum_e KV[b,h,d,e] * W[o*Dm + h*64 + e]
// Stores tf32 bit patterns (kernel D's B operand, RNA-rounded).
// ---------------------------------------------------------------------------
__global__ __launch_bounds__(128) void w2_kernel(const float* __restrict__ W)
{
    __shared__ float KVt[64][64];
    __shared__ float WsT[64][128];

    const int bh = blockIdx.x;
    const int b = bh >> 4, h = bh & 15;
    const int t = threadIdx.x;
    const int o_base = blockIdx.y * 128;

#pragma unroll
    for (int i = 0; i < 8; i++) {
        int idx = t + i * 128;
        int rd = idx & 63;
        int c4 = (idx >> 6) * 4;
        float4 v = *(const float4*)(g_KV + (size_t)bh * 4096 + rd * 64 + c4);
        KVt[c4 + 0][rd] = v.x; KVt[c4 + 1][rd] = v.y;
        KVt[c4 + 2][rd] = v.z; KVt[c4 + 3][rd] = v.w;
    }
#pragma unroll
    for (int i = 0; i < 16; i++) {
        int idx = t + i * 128;
        int ro = idx & 127;
        int c4 = (idx >> 7) * 4;
        float4 v = *(const float4*)(W + (size_t)(o_base + ro) * Dm + h * HD + c4);
        WsT[c4 + 0][ro] = v.x; WsT[c4 + 1][ro] = v.y;
        WsT[c4 + 2][ro] = v.z; WsT[c4 + 3][ro] = v.w;
    }
    __syncthreads();

    const int d0 = (t & 7) * 8;
    const int o0 = (t >> 3) * 8;
    float acc[8][8] = {};
#pragma unroll 4
    for (int e = 0; e < 64; e++) {
        float ww[8], kk[8];
        *(float4*)&ww[0] = *(const float4*)&WsT[e][o0];
        *(float4*)&ww[4] = *(const float4*)&WsT[e][o0 + 4];
        *(float4*)&kk[0] = *(const float4*)&KVt[e][d0];
        *(float4*)&kk[4] = *(const float4*)&KVt[e][d0 + 4];
#pragma unroll
        for (int i = 0; i < 8; i++)
#pragma unroll
            for (int j = 0; j < 8; j++)
                acc[i][j] += ww[i] * kk[j];
    }

#pragma unroll
    for (int i = 0; i < 8; i++) {
        float* dst = g_W2 + ((size_t)b * Dm + (o_base + o0 + i)) * Dm + h * HD + d0;
#pragma unroll
        for (int jj = 0; jj < 2; jj++) {
            float4 o;
            o.x = __uint_as_float(f2tf32(acc[i][jj * 4 + 0]));
            o.y = __uint_as_float(f2tf32(acc[i][jj * 4 + 1]));
            o.z = __uint_as_float(f2tf32(acc[i][jj * 4 + 2]));
            o.w = __uint_as_float(f2tf32(acc[i][jj * 4 + 3]));
            *(float4*)(dst + jj * 4) = o;
        }
    }
}

// ---------------------------------------------------------------------------
// Kernel D: out[b,m,n] = sum_k Q[b,m,k]*W2[b,n,k] + bias[n]
// Raw fp32 A bits / RNA-tf32 B; per-stage mbarrier flow control:
//   full[s] (count 256, armed by cp.async.mbarrier.arrive.NOINC) = data ready
//   empty[s] (count 8, one arrive per warp) = stage reusable
// ---------------------------------------------------------------------------
__global__ __launch_bounds__(256, 2) void out_gemm_tc(
    const float* __restrict__ Q, const float* __restrict__ bias,
    float* __restrict__ Out)
{
    extern __shared__ float smem[];
    __shared__ alignas(8) uint64_t s_full[NS];
    __shared__ alignas(8) uint64_t s_empty[NS];

    const int t   = threadIdx.x;
    const int wid = t >> 5;
    const int lid = t & 31;
    const int g   = lid >> 2;
    const int tig = lid & 3;
    const int wm  = wid >> 2;
    const int wn  = wid & 3;

    const int m0 = blockIdx.x * TM;
    const int n0 = blockIdx.y * TN;
    const int b  = blockIdx.z;

    const float* Ag = Q    + (size_t)b * Sl * Dm + (size_t)m0 * Dm;
    const float* Bg = g_W2 + (size_t)b * Dm * Dm + (size_t)n0 * Dm;

    const uint32_t u0 = smem_u32(smem);
    const uint32_t fb0 = smem_u32(&s_full[0]);
    const uint32_t eb0 = smem_u32(&s_empty[0]);

    if (t == 0) {
#pragma unroll
        for (int s = 0; s < NS; s++) {
            MBAR_INIT(fb0 + s * 8, 256);
            MBAR_INIT(eb0 + s * 8, 8);
        }
    }
    __syncthreads();

    auto load_stage = [&](int s, int k0) {
        uint32_t uA = u0 + (uint32_t)(s * STAGE_FLOATS) * 4;
        uint32_t uB = uA + A_FLOATS * 4;
#pragma unroll
        for (int i = 0; i < 4; i++) {
            int idx = t + (i << 8);
            int row = idx >> 3, c = idx & 7;
            cp16(uA + row * (KPAD * 4) + c * 16, Ag + (size_t)row * Dm + k0 + c * 4);
        }
#pragma unroll
        for (int i = 0; i < 4; i++) {
            int idx = t + (i << 8);
            int row = idx >> 3, c = idx & 7;
            cp16(uB + row * (KPAD * 4) + c * 16, Bg + (size_t)row * Dm + k0 + c * 4);
        }
    };

    float acc[4][4][4] = {};

    // prologue: fill all NS stages; arm full[s] via noinc arrive-on-complete
#pragma unroll
    for (int s = 0; s < NS; s++) {
        load_stage(s, s * BK);
        CPASYNC_MBAR_ARRIVE(fb0 + s * 8);
    }

    const uint32_t aBase = (uint32_t)(wm * 64 + (lid & 15)) * (KPAD * 4)
                         + (uint32_t)(lid >> 4) * 16;
    const uint32_t bBase = (uint32_t)(wn * 32 + ((lid >> 4) << 3) + (lid & 7)) * (KPAD * 4)
                         + (uint32_t)((lid >> 3) & 1) * 16;

    int s = 0, fp = 0, ep = 0;
    for (int i = 0; i < NCHUNK; i++) {
        MBAR_WAIT(fb0 + s * 8, fp);                 // chunk i data ready

        uint32_t uA = u0 + (uint32_t)(s * STAGE_FLOATS) * 4;
        uint32_t uB = uA + A_FLOATS * 4;

#pragma unroll
        for (int ks = 0; ks < 4; ks++) {
            uint32_t af[4][4];
#pragma unroll
            for (int mi = 0; mi < 4; mi++)
                ldsm4(af[mi], uA + aBase + mi * 16 * (KPAD * 4) + ks * 32);
            uint32_t bf[2][4];
#pragma unroll
            for (int p = 0; p < 2; p++)
                ldsm4(bf[p], uB + bBase + p * 16 * (KPAD * 4) + ks * 32);
#pragma unroll
            for (int mi = 0; mi < 4; mi++)
#pragma unroll
                for (int ni = 0; ni < 4; ni++) {
                    const int p = ni >> 1, q = (ni & 1) * 2;
                    mma_tf32_16n8k8(acc[mi][ni],
                                    af[mi][0], af[mi][1], af[mi][2], af[mi][3],
                                    bf[p][q], bf[p][q + 1]);
                }
        }

        if (lid == 0) MBAR_ARRIVE(eb0 + s * 8);     // this warp done with stage s

        if (i + NS < NCHUNK) {
            MBAR_WAIT(eb0 + s * 8, ep);             // all 8 warps done chunk i
            load_stage(s, (i + NS) * BK);
            CPASYNC_MBAR_ARRIVE(fb0 + s * 8);       // arms chunk i+NS
        }

        if (++s == NS) { s = 0; fp ^= 1; ep ^= 1; }
    }

    float* C = Out + (size_t)b * Sl * Dm;
#pragma unroll
    for (int mi = 0; mi < 4; mi++) {
        int row = m0 + wm * 64 + mi * 16 + g;
#pragma unroll
        for (int ni = 0; ni < 4; ni++) {
            int col = n0 + wn * 32 + ni * 8 + tig * 2;
            float bx = bias[col], by = bias[col + 1];
            float2 r0 = { acc[mi][ni][0] + bx, acc[mi][ni][1] + by };
            float2 r1 = { acc[mi][ni][2] + bx, acc[mi][ni][3] + by };
            *(float2*)(C + (size_t)row * Dm + col)       = r0;
            *(float2*)(C + (size_t)(row + 8) * Dm + col) = r1;
        }
    }
}

// ---------------------------------------------------------------------------
extern "C" void kernel_launch(void* const* d_in, const int* in_sizes, int n_in,
                              void* d_out, int out_size)
{
    const float* Q    = (const float*)d_in[0];
    const float* K    = (const float*)d_in[1];
    const float* V    = (const float*)d_in[2];
    const float* Wout = (const float*)d_in[3];
    const float* bout = (const float*)d_in[4];
    float* Out = (float*)d_out;

    static bool attr_done = false;
    if (!attr_done) {
        cudaFuncSetAttribute(out_gemm_tc,
                             cudaFuncAttributeMaxDynamicSharedMemorySize, SMEM_DYN);
        attr_done = true;
    }

    kv_tc_kernel<<<dim3(BH * KVSPLIT), 256>>>(K, V);
    kv_reduce_kernel<<<dim3(BH * HD * HD / 256), 256>>>();
    w2_kernel<<<dim3(BH, Dm / 128), 128>>>(Wout);
    out_gemm_tc<<<dim3(Sl / TM, Dm / TN, Bsz), 256, SMEM_DYN>>>(Q, bout, Out);
}